// round 13
// baseline (speedup 1.0000x reference)
#include <cuda_runtime.h>
#include <cuda_fp16.h>
#include <cstdint>

// Shapes (fixed): B=4, T=2048, C=2048, nH=16, hd=128
// Output = concat(y [B,T,C], new_k [B,nH,T,hd], new_v [B,nH,T,hd])

#define C_DIM   2048
#define T_DIM   2048
#define B_DIM   4
#define NH      16
#define HD      128
#define MTOT    (B_DIM * T_DIM)         // 8192
#define YELEMS  (B_DIM * T_DIM * C_DIM) // 16777216

// fp16 staging buffers
__device__ __half g_xh[YELEMS];
__device__ __half g_wqkvh[3 * C_DIM * C_DIM];
__device__ __half g_wouth[C_DIM * C_DIM];
__device__ __half g_qh[YELEMS];     // q [B,nH,T,hd]
__device__ __half g_kh[YELEMS];     // k fp16 copy for attn
__device__ __half g_vh[YELEMS];     // v fp16 copy for attn
__device__ __half g_yh[YELEMS];     // attn out [B,T,C]

__device__ __forceinline__ uint32_t pkh(float lo, float hi) {
    __half2 h = __floats2half2_rn(lo, hi);
    return *reinterpret_cast<uint32_t*>(&h);
}

__device__ __forceinline__ void mma_f16(float* c, const uint32_t* a,
                                        const uint32_t* b) {
    asm volatile(
        "mma.sync.aligned.m16n8k16.row.col.f32.f16.f16.f32 "
        "{%0,%1,%2,%3},{%4,%5,%6,%7},{%8,%9},{%0,%1,%2,%3};"
        : "+f"(c[0]), "+f"(c[1]), "+f"(c[2]), "+f"(c[3])
        : "r"(a[0]), "r"(a[1]), "r"(a[2]), "r"(a[3]), "r"(b[0]), "r"(b[1]));
}

__device__ __forceinline__ void ldsm4(uint32_t& r0, uint32_t& r1,
                                      uint32_t& r2, uint32_t& r3, uint32_t a) {
    asm volatile("ldmatrix.sync.aligned.m8n8.x4.shared.b16 {%0,%1,%2,%3},[%4];"
                 : "=r"(r0), "=r"(r1), "=r"(r2), "=r"(r3) : "r"(a));
}
__device__ __forceinline__ void ldsm4t(uint32_t& r0, uint32_t& r1,
                                       uint32_t& r2, uint32_t& r3, uint32_t a) {
    asm volatile(
        "ldmatrix.sync.aligned.m8n8.x4.trans.shared.b16 {%0,%1,%2,%3},[%4];"
        : "=r"(r0), "=r"(r1), "=r"(r2), "=r"(r3) : "r"(a));
}

// .ca: keep lines in L1 — weights/x/KV tiles have heavy same-SM reuse
__device__ __forceinline__ void cpasync16(uint32_t smem_addr, const void* g) {
    asm volatile("cp.async.ca.shared.global [%0], [%1], 16;"
                 :: "r"(smem_addr), "l"(g));
}

__device__ __forceinline__ uint32_t smem_u32(const void* p) {
    return (uint32_t)__cvta_generic_to_shared(p);
}

// ---------------------------------------------------------------------------
// fp32 -> fp16 conversion, all three tensors in ONE launch
// ---------------------------------------------------------------------------
#define N4_X   (YELEMS / 4)                    // 4194304
#define N4_WQ  (3 * C_DIM * C_DIM / 4)         // 3145728
#define N4_WO  (C_DIM * C_DIM / 4)             // 1048576

__global__ __launch_bounds__(256) void cvt_all_kernel(
    const float4* __restrict__ x,  uint2* __restrict__ xh,
    const float4* __restrict__ wq, uint2* __restrict__ wqh,
    const float4* __restrict__ wo, uint2* __restrict__ woh)
{
    const int total = N4_X + N4_WQ + N4_WO;
    for (int i = blockIdx.x * blockDim.x + threadIdx.x; i < total;
         i += gridDim.x * blockDim.x) {
        const float4* s;
        uint2* d;
        int idx;
        if (i < N4_X)              { s = x;  d = xh;  idx = i; }
        else if (i < N4_X + N4_WQ) { s = wq; d = wqh; idx = i - N4_X; }
        else                       { s = wo; d = woh; idx = i - N4_X - N4_WQ; }
        float4 v = s[idx];
        uint2 o;
        o.x = pkh(v.x, v.y);
        o.y = pkh(v.z, v.w);
        d[idx] = o;
    }
}

// ---------------------------------------------------------------------------
// FP16 GEMM: 128x128x32, 256 threads, warp 64x32, m16n8k16.
// 5-stage cp.async ring (prefetch distance 4), one barrier/iter, 2 CTAs/SM.
// ---------------------------------------------------------------------------
#define BM 128
#define BN 128
#define BK 32
#define LDH 40
#define AWH (BM * LDH)                 // 5120 halves / stage / matrix
#define NSTG 5
#define GEMM_SMEM (2 * NSTG * AWH * 2) // 102400 B

template <int MODE>
__global__ __launch_bounds__(256, 2) void mma_gemm(
    const __half* __restrict__ A,     // [M,2048]
    const __half* __restrict__ W,     // [N,2048]
    const float* __restrict__ bias,
    float* __restrict__ out0,         // MODE0: k ; MODE1: y
    float* __restrict__ out1)         // MODE0: v
{
    const int K = C_DIM;
    extern __shared__ __half hsm[];

    const int tid  = threadIdx.x;
    const int lane = tid & 31;
    const int wid  = tid >> 5;
    const int wm   = wid >> 2;        // 0..1
    const int wn   = wid & 3;         // 0..3
    const int m0   = blockIdx.y * BM;
    const int n0   = blockIdx.x * BN;

    const int g   = lane >> 3;
    const int l8  = lane & 7;

    const int crow = tid >> 2;        // 0..63
    const int ckq  = (tid & 3) << 3;  // 0,8,16,24 halves

    float acc[4][4][4];
#pragma unroll
    for (int i = 0; i < 4; i++)
#pragma unroll
        for (int j = 0; j < 4; j++)
#pragma unroll
            for (int c = 0; c < 4; c++) acc[i][j][c] = 0.0f;

    auto issue_stage = [&](int s, int k0) {
        __half* as = hsm + s * AWH;
        __half* bs = hsm + NSTG * AWH + s * AWH;
#pragma unroll
        for (int r = 0; r < 2; r++) {
            int row = crow + r * 64;
            cpasync16(smem_u32(&as[row * LDH + ckq]),
                      &A[(size_t)(m0 + row) * K + k0 + ckq]);
            cpasync16(smem_u32(&bs[row * LDH + ckq]),
                      &W[(size_t)(n0 + row) * K + k0 + ckq]);
        }
        asm volatile("cp.async.commit_group;");
    };

    const int NIT = K / BK;           // 64
    issue_stage(0, 0);
    issue_stage(1, BK);
    issue_stage(2, 2 * BK);
    issue_stage(3, 3 * BK);

    int buf = 0;
    for (int i = 0; i < NIT; i++) {
        // stage i must be complete: pending-after = min(NIT-1-i, 3)
        const int rem = NIT - 1 - i;
        if (rem >= 3) {
            asm volatile("cp.async.wait_group 3;");
        } else if (rem == 2) {
            asm volatile("cp.async.wait_group 2;");
        } else if (rem == 1) {
            asm volatile("cp.async.wait_group 1;");
        } else {
            asm volatile("cp.async.wait_group 0;");
        }
        __syncthreads();
        if (i + 4 < NIT) {
            int s = (i + 4) % NSTG;   // == buffer of stage i-1, certified free
            issue_stage(s, (i + 4) * BK);
        }

        const __half* as = hsm + buf * AWH;
        const __half* bs = hsm + NSTG * AWH + buf * AWH;
#pragma unroll
        for (int kb = 0; kb < BK; kb += 16) {
            uint32_t af[4][4], bf[2][4];
#pragma unroll
            for (int am = 0; am < 4; am++) {
                int row = wm * 64 + am * 16 + (g & 1) * 8 + l8;
                int col = kb + (g >> 1) * 8;
                ldsm4(af[am][0], af[am][1], af[am][2], af[am][3],
                      smem_u32(&as[row * LDH + col]));
            }
#pragma unroll
            for (int ap = 0; ap < 2; ap++) {
                int row = wn * 32 + ap * 16 + (g >> 1) * 8 + l8;
                int col = kb + (g & 1) * 8;
                ldsm4(bf[ap][0], bf[ap][1], bf[ap][2], bf[ap][3],
                      smem_u32(&bs[row * LDH + col]));
            }
#pragma unroll
            for (int am = 0; am < 4; am++)
#pragma unroll
                for (int an = 0; an < 4; an++)
                    mma_f16(acc[am][an], af[am], &bf[an >> 1][(an & 1) * 2]);
        }
        buf = (buf + 1) % NSTG;
    }

    // ---- epilogue ----
    if (MODE == 0) {
        const int seg = n0 >> 11;           // 0=q, 1=k, 2=v
        const int hh  = (n0 & 2047) >> 7;
#pragma unroll
        for (int am = 0; am < 4; am++) {
#pragma unroll
            for (int cp = 0; cp < 2; cp++) {
                int row = wm * 64 + am * 16 + (lane >> 2) + cp * 8;
                int m = m0 + row;
                int b_ = m >> 11;
                int t  = m & 2047;
                size_t base = (((size_t)(b_ * NH + hh) * T_DIM) + t) * HD;
                if (seg == 0) {
                    __half* dstrow = g_qh + base;
#pragma unroll
                    for (int an = 0; an < 4; an++) {
                        int cl = wn * 32 + an * 8 + (lane & 3) * 2;
                        uint32_t v = pkh(acc[am][an][cp * 2 + 0] + bias[n0 + cl],
                                         acc[am][an][cp * 2 + 1] + bias[n0 + cl + 1]);
                        *reinterpret_cast<uint32_t*>(&dstrow[cl]) = v;
                    }
                } else {
                    float* dstrow = ((seg == 1) ? out0 : out1) + base;
                    __half* hrow  = ((seg == 1) ? g_kh : g_vh) + base;
#pragma unroll
                    for (int an = 0; an < 4; an++) {
                        int cl = wn * 32 + an * 8 + (lane & 3) * 2;
                        float2 v;
                        v.x = acc[am][an][cp * 2 + 0] + bias[n0 + cl];
                        v.y = acc[am][an][cp * 2 + 1] + bias[n0 + cl + 1];
                        *reinterpret_cast<float2*>(&dstrow[cl]) = v;
                        *reinterpret_cast<uint32_t*>(&hrow[cl]) = pkh(v.x, v.y);
                    }
                }
            }
        }
    } else {
#pragma unroll
        for (int am = 0; am < 4; am++) {
#pragma unroll
            for (int cp = 0; cp < 2; cp++) {
                int row = wm * 64 + am * 16 + (lane >> 2) + cp * 8;
                int m = m0 + row;
                float* dstrow = out0 + (size_t)m * C_DIM + n0;
#pragma unroll
                for (int an = 0; an < 4; an++) {
                    int cl = wn * 32 + an * 8 + (lane & 3) * 2;
                    float2 v;
                    v.x = acc[am][an][cp * 2 + 0] + bias[n0 + cl];
                    v.y = acc[am][an][cp * 2 + 1] + bias[n0 + cl + 1];
                    *reinterpret_cast<float2*>(&dstrow[cl]) = v;
                }
            }
        }
    }
}

// ---------------------------------------------------------------------------
// FP16 MMA flash attention: register-P, async double-buffered K/V,
// heavy-first scheduling, 2 CTAs/SM. BQ=128, BK=64, 256 threads.
// ---------------------------------------------------------------------------
#define ALH 136

__global__ __launch_bounds__(256, 2) void attn_mma_kernel(int dummy)
{
    extern __shared__ __half sh[];
    __half* Qs = sh;                       // 128 x 136
    __half* Ks = Qs + 128 * ALH;           // 2 x 64 x 136
    __half* Vs = Ks + 2 * 64 * ALH;        // 2 x 64 x 136

    const int tid  = threadIdx.x;
    const int lane = tid & 31;
    const int w    = tid >> 5;
    const int g    = lane >> 3;
    const int l8   = lane & 7;
    const int iq   = (int)gridDim.x - 1 - (int)blockIdx.x;  // heavy first
    const int bh   = blockIdx.y;
    const int b    = bh >> 4;
    const int h    = bh & 15;

    const __half* qp = g_qh + ((size_t)bh * T_DIM + iq * 128) * HD;
    const __half* kp = g_kh + (size_t)bh * T_DIM * HD;
    const __half* vp = g_vh + (size_t)bh * T_DIM * HD;

    const int jmax = 2 * iq + 1;

    auto issue_kv = [&](int bufi, int j) {
        const __half* kb = kp + (size_t)j * 64 * HD;
        const __half* vb = vp + (size_t)j * 64 * HD;
        __half* Kd = Ks + bufi * 64 * ALH;
        __half* Vd = Vs + bufi * 64 * ALH;
#pragma unroll
        for (int r = 0; r < 4; r++) {
            int idx = tid + r * 256;
            int row = idx >> 4;
            int c   = (idx & 15) << 3;
            cpasync16(smem_u32(&Kd[row * ALH + c]), &kb[row * HD + c]);
            cpasync16(smem_u32(&Vd[row * ALH + c]), &vb[row * HD + c]);
        }
        asm volatile("cp.async.commit_group;");
    };

    issue_kv(0, 0);

#pragma unroll
    for (int r = 0; r < 8; r++) {
        int idx = tid + r * 256;
        int row = idx >> 4;
        int c   = (idx & 15) << 3;
        *reinterpret_cast<uint4*>(&Qs[row * ALH + c]) =
            *reinterpret_cast<const uint4*>(&qp[row * HD + c]);
    }
    __syncthreads();

    const int r0 = lane >> 2;
    float m_i[2] = {-1e30f, -1e30f};
    float l_i[2] = {0.0f, 0.0f};
    float oacc[16][4];
#pragma unroll
    for (int na = 0; na < 16; na++)
#pragma unroll
        for (int c = 0; c < 4; c++) oacc[na][c] = 0.0f;

    const float scale = 0.08838834764831843f;
    const int qrow_frag = w * 16 + (g & 1) * 8 + l8;

    for (int j = 0; j <= jmax; j++) {
        asm volatile("cp.async.wait_group 0;");
        __syncthreads();
        if (j < jmax) issue_kv((j + 1) & 1, j + 1);

        const __half* Kb = Ks + (j & 1) * 64 * ALH;
        const __half* Vb = Vs + (j & 1) * 64 * ALH;

        float sacc[8][4];
#pragma unroll
        for (int na = 0; na < 8; na++)
#pragma unroll
            for (int c = 0; c < 4; c++) sacc[na][c] = 0.0f;

#pragma unroll
        for (int ks = 0; ks < 8; ks++) {
            uint32_t qf[4];
            {
                int col = ks * 16 + (g >> 1) * 8;
                ldsm4(qf[0], qf[1], qf[2], qf[3],
                      smem_u32(&Qs[qrow_frag * ALH + col]));
            }
#pragma unroll
            for (int np = 0; np < 4; np++) {
                uint32_t bf[4];
                int row = np * 16 + (g >> 1) * 8 + l8;
                int col = ks * 16 + (g & 1) * 8;
                ldsm4(bf[0], bf[1], bf[2], bf[3],
                      smem_u32(&Kb[row * ALH + col]));
                mma_f16(sacc[2 * np],     qf, &bf[0]);
                mma_f16(sacc[2 * np + 1], qf, &bf[2]);
            }
        }

#pragma unroll
        for (int na = 0; na < 8; na++)
#pragma unroll
            for (int c = 0; c < 4; c++) sacc[na][c] *= scale;
        if (j >= 2 * iq) {
            int qrow0 = iq * 128 + w * 16 + r0;
#pragma unroll
            for (int na = 0; na < 8; na++) {
                int col = j * 64 + na * 8 + 2 * (lane & 3);
                if (col > qrow0)         sacc[na][0] = -1e30f;
                if (col + 1 > qrow0)     sacc[na][1] = -1e30f;
                if (col > qrow0 + 8)     sacc[na][2] = -1e30f;
                if (col + 1 > qrow0 + 8) sacc[na][3] = -1e30f;
            }
        }

        float mt[2] = {-1e30f, -1e30f};
#pragma unroll
        for (int na = 0; na < 8; na++) {
            mt[0] = fmaxf(mt[0], fmaxf(sacc[na][0], sacc[na][1]));
            mt[1] = fmaxf(mt[1], fmaxf(sacc[na][2], sacc[na][3]));
        }
#pragma unroll
        for (int off = 1; off <= 2; off <<= 1) {
            mt[0] = fmaxf(mt[0], __shfl_xor_sync(0xffffffffu, mt[0], off));
            mt[1] = fmaxf(mt[1], __shfl_xor_sync(0xffffffffu, mt[1], off));
        }
        float mnew0 = fmaxf(m_i[0], mt[0]);
        float mnew1 = fmaxf(m_i[1], mt[1]);
        float alpha0 = __expf(m_i[0] - mnew0);
        float alpha1 = __expf(m_i[1] - mnew1);
        m_i[0] = mnew0; m_i[1] = mnew1;

        float sum0 = 0.0f, sum1 = 0.0f;
#pragma unroll
        for (int na = 0; na < 8; na++) {
            sacc[na][0] = __expf(sacc[na][0] - mnew0);
            sacc[na][1] = __expf(sacc[na][1] - mnew0);
            sacc[na][2] = __expf(sacc[na][2] - mnew1);
            sacc[na][3] = __expf(sacc[na][3] - mnew1);
            sum0 += sacc[na][0] + sacc[na][1];
            sum1 += sacc[na][2] + sacc[na][3];
        }
#pragma unroll
        for (int off = 1; off <= 2; off <<= 1) {
            sum0 += __shfl_xor_sync(0xffffffffu, sum0, off);
            sum1 += __shfl_xor_sync(0xffffffffu, sum1, off);
        }
        l_i[0] = l_i[0] * alpha0 + sum0;
        l_i[1] = l_i[1] * alpha1 + sum1;
#pragma unroll
        for (int na = 0; na < 16; na++) {
            oacc[na][0] *= alpha0; oacc[na][1] *= alpha0;
            oacc[na][2] *= alpha1; oacc[na][3] *= alpha1;
        }

#pragma unroll
        for (int kc = 0; kc < 4; kc++) {
            uint32_t pa[4];
            pa[0] = pkh(sacc[2 * kc][0],     sacc[2 * kc][1]);
            pa[1] = pkh(sacc[2 * kc][2],     sacc[2 * kc][3]);
            pa[2] = pkh(sacc[2 * kc + 1][0], sacc[2 * kc + 1][1]);
            pa[3] = pkh(sacc[2 * kc + 1][2], sacc[2 * kc + 1][3]);
#pragma unroll
            for (int ng = 0; ng < 8; ng++) {
                uint32_t vf[4];
                int row = kc * 16 + (g & 1) * 8 + l8;
                int col = ng * 16 + (g >> 1) * 8;
                ldsm4t(vf[0], vf[1], vf[2], vf[3],
                       smem_u32(&Vb[row * ALH + col]));
                mma_f16(oacc[2 * ng],     pa, &vf[0]);
                mma_f16(oacc[2 * ng + 1], pa, &vf[2]);
            }
        }
    }

    float inv0 = 1.0f / l_i[0];
    float inv1 = 1.0f / l_i[1];
    int t0 = iq * 128 + w * 16 + r0;
    int t1 = t0 + 8;
    __half* dst0 = g_yh + ((size_t)(b * T_DIM + t0) * C_DIM) + h * HD;
    __half* dst1 = g_yh + ((size_t)(b * T_DIM + t1) * C_DIM) + h * HD;
#pragma unroll
    for (int na = 0; na < 16; na++) {
        int col = na * 8 + 2 * (lane & 3);
        *reinterpret_cast<uint32_t*>(&dst0[col]) =
            pkh(oacc[na][0] * inv0, oacc[na][1] * inv0);
        *reinterpret_cast<uint32_t*>(&dst1[col]) =
            pkh(oacc[na][2] * inv1, oacc[na][3] * inv1);
    }
}

// ---------------------------------------------------------------------------
extern "C" void kernel_launch(void* const* d_in, const int* in_sizes, int n_in,
                              void* d_out, int out_size)
{
    const float* x    = (const float*)d_in[0];
    const float* Wqkv = (const float*)d_in[1];
    const float* bqkv = (const float*)d_in[2];
    const float* Wout = (const float*)d_in[3];
    const float* bout = (const float*)d_in[4];

    float* y    = (float*)d_out;
    float* kout = y + YELEMS;
    float* vout = y + 2 * YELEMS;

    __half *xh, *wqkvh, *wouth, *yh;
    cudaGetSymbolAddress((void**)&xh,    g_xh);
    cudaGetSymbolAddress((void**)&wqkvh, g_wqkvh);
    cudaGetSymbolAddress((void**)&wouth, g_wouth);
    cudaGetSymbolAddress((void**)&yh,    g_yh);

    const int attn_smem = (128 + 128 + 128) * ALH * 2;   // 104448
    cudaFuncSetAttribute(attn_mma_kernel,
                         cudaFuncAttributeMaxDynamicSharedMemorySize, attn_smem);
    cudaFuncSetAttribute(mma_gemm<0>,
                         cudaFuncAttributeMaxDynamicSharedMemorySize, GEMM_SMEM);
    cudaFuncSetAttribute(mma_gemm<1>,
                         cudaFuncAttributeMaxDynamicSharedMemorySize, GEMM_SMEM);

    // 0) fp16 pre-conversion (single launch, wider grid)
    cvt_all_kernel<<<8192, 256>>>((const float4*)x, (uint2*)xh,
                                  (const float4*)Wqkv, (uint2*)wqkvh,
                                  (const float4*)Wout, (uint2*)wouth);

    // 1) QKV projection (fp16 MMA, 5-stage ring, .ca, 2 CTA/SM) + scatter
    mma_gemm<0><<<dim3(3 * C_DIM / BN, MTOT / BM), 256, GEMM_SMEM>>>(
        xh, wqkvh, bqkv, kout, vout);

    // 2) causal flash attention (register P, async K/V, 2 CTA/SM) -> g_yh
    attn_mma_kernel<<<dim3(T_DIM / 128, B_DIM * NH), 256, attn_smem>>>(0);

    // 3) output projection -> y
    mma_gemm<1><<<dim3(C_DIM / BN, MTOT / BM), 256, GEMM_SMEM>>>(
        yh, wouth, bout, y, nullptr);
}

// round 14
// speedup vs baseline: 1.2361x; 1.2361x over previous
#include <cuda_runtime.h>
#include <cuda_fp16.h>
#include <cstdint>

// Shapes (fixed): B=4, T=2048, C=2048, nH=16, hd=128
// Output = concat(y [B,T,C], new_k [B,nH,T,hd], new_v [B,nH,T,hd])

#define C_DIM   2048
#define T_DIM   2048
#define B_DIM   4
#define NH      16
#define HD      128
#define MTOT    (B_DIM * T_DIM)         // 8192
#define YELEMS  (B_DIM * T_DIM * C_DIM) // 16777216

// fp16 staging buffers
__device__ __half g_xh[YELEMS];
__device__ __half g_wqkvh[3 * C_DIM * C_DIM];
__device__ __half g_wouth[C_DIM * C_DIM];
__device__ __half g_qh[YELEMS];     // q [B,nH,T,hd]
__device__ __half g_kh[YELEMS];     // k fp16 copy for attn
__device__ __half g_vh[YELEMS];     // v fp16 copy for attn
__device__ __half g_yh[YELEMS];     // attn out [B,T,C]

__device__ __forceinline__ uint32_t pkh(float lo, float hi) {
    __half2 h = __floats2half2_rn(lo, hi);
    return *reinterpret_cast<uint32_t*>(&h);
}

__device__ __forceinline__ void mma_f16(float* c, const uint32_t* a,
                                        const uint32_t* b) {
    asm volatile(
        "mma.sync.aligned.m16n8k16.row.col.f32.f16.f16.f32 "
        "{%0,%1,%2,%3},{%4,%5,%6,%7},{%8,%9},{%0,%1,%2,%3};"
        : "+f"(c[0]), "+f"(c[1]), "+f"(c[2]), "+f"(c[3])
        : "r"(a[0]), "r"(a[1]), "r"(a[2]), "r"(a[3]), "r"(b[0]), "r"(b[1]));
}

__device__ __forceinline__ void ldsm4(uint32_t& r0, uint32_t& r1,
                                      uint32_t& r2, uint32_t& r3, uint32_t a) {
    asm volatile("ldmatrix.sync.aligned.m8n8.x4.shared.b16 {%0,%1,%2,%3},[%4];"
                 : "=r"(r0), "=r"(r1), "=r"(r2), "=r"(r3) : "r"(a));
}
__device__ __forceinline__ void ldsm4t(uint32_t& r0, uint32_t& r1,
                                       uint32_t& r2, uint32_t& r3, uint32_t a) {
    asm volatile(
        "ldmatrix.sync.aligned.m8n8.x4.trans.shared.b16 {%0,%1,%2,%3},[%4];"
        : "=r"(r0), "=r"(r1), "=r"(r2), "=r"(r3) : "r"(a));
}

// .cg: bypass L1 — L1/shared bandwidth belongs to ldmatrix (R13 lesson)
__device__ __forceinline__ void cpasync16(uint32_t smem_addr, const void* g) {
    asm volatile("cp.async.cg.shared.global [%0], [%1], 16;"
                 :: "r"(smem_addr), "l"(g));
}

__device__ __forceinline__ uint32_t smem_u32(const void* p) {
    return (uint32_t)__cvta_generic_to_shared(p);
}

// ---------------------------------------------------------------------------
// fp32 -> fp16 conversion, all three tensors in ONE launch
// ---------------------------------------------------------------------------
#define N4_X   (YELEMS / 4)                    // 4194304
#define N4_WQ  (3 * C_DIM * C_DIM / 4)         // 3145728
#define N4_WO  (C_DIM * C_DIM / 4)             // 1048576

__global__ __launch_bounds__(256) void cvt_all_kernel(
    const float4* __restrict__ x,  uint2* __restrict__ xh,
    const float4* __restrict__ wq, uint2* __restrict__ wqh,
    const float4* __restrict__ wo, uint2* __restrict__ woh)
{
    const int total = N4_X + N4_WQ + N4_WO;
    for (int i = blockIdx.x * blockDim.x + threadIdx.x; i < total;
         i += gridDim.x * blockDim.x) {
        const float4* s;
        uint2* d;
        int idx;
        if (i < N4_X)              { s = x;  d = xh;  idx = i; }
        else if (i < N4_X + N4_WQ) { s = wq; d = wqh; idx = i - N4_X; }
        else                       { s = wo; d = woh; idx = i - N4_X - N4_WQ; }
        float4 v = s[idx];
        uint2 o;
        o.x = pkh(v.x, v.y);
        o.y = pkh(v.z, v.w);
        d[idx] = o;
    }
}

// ---------------------------------------------------------------------------
// FP16 GEMM (R12-proven core): 128x128x32, 256 threads, warp 64x32, m16n8k16.
// 4-stage cp.async ring (.cg), one barrier/iter, 2 CTAs/SM.
// NEW: 1D grid with GROUP_M=16 L2-locality swizzle (Triton-style).
// ---------------------------------------------------------------------------
#define BM 128
#define BN 128
#define BK 32
#define LDH 40
#define AWH (BM * LDH)                 // 5120 halves / stage / matrix
#define NSTG 4
#define GEMM_SMEM (2 * NSTG * AWH * 2) // 81920 B
#define GROUP_M 16

template <int MODE>
__global__ __launch_bounds__(256, 2) void mma_gemm(
    const __half* __restrict__ A,     // [M,2048]
    const __half* __restrict__ W,     // [N,2048]
    const float* __restrict__ bias,
    float* __restrict__ out0,         // MODE0: k ; MODE1: y
    float* __restrict__ out1)         // MODE0: v
{
    const int K = C_DIM;
    extern __shared__ __half hsm[];

    // --- L2 grid swizzle: wave covers ~GROUP_M x (wave/GROUP_M) tile block ---
    constexpr int NPM = MTOT / BM;                     // 64
    constexpr int NPN = (MODE == 0) ? (3 * C_DIM / BN) // 48
                                    : (C_DIM / BN);    // 16
    const int bid        = blockIdx.x;                 // 0 .. NPM*NPN-1
    const int group_size = GROUP_M * NPN;
    const int group_id   = bid / group_size;
    const int pid_in     = bid % group_size;
    const int pid_m      = group_id * GROUP_M + (pid_in % GROUP_M);
    const int pid_n      = pid_in / GROUP_M;
    const int m0         = pid_m * BM;
    const int n0         = pid_n * BN;

    const int tid  = threadIdx.x;
    const int lane = tid & 31;
    const int wid  = tid >> 5;
    const int wm   = wid >> 2;        // 0..1
    const int wn   = wid & 3;         // 0..3

    const int g   = lane >> 3;
    const int l8  = lane & 7;

    const int crow = tid >> 2;        // 0..63
    const int ckq  = (tid & 3) << 3;  // 0,8,16,24 halves

    float acc[4][4][4];
#pragma unroll
    for (int i = 0; i < 4; i++)
#pragma unroll
        for (int j = 0; j < 4; j++)
#pragma unroll
            for (int c = 0; c < 4; c++) acc[i][j][c] = 0.0f;

    auto issue_stage = [&](int s, int k0) {
        __half* as = hsm + s * AWH;
        __half* bs = hsm + NSTG * AWH + s * AWH;
#pragma unroll
        for (int r = 0; r < 2; r++) {
            int row = crow + r * 64;
            cpasync16(smem_u32(&as[row * LDH + ckq]),
                      &A[(size_t)(m0 + row) * K + k0 + ckq]);
            cpasync16(smem_u32(&bs[row * LDH + ckq]),
                      &W[(size_t)(n0 + row) * K + k0 + ckq]);
        }
        asm volatile("cp.async.commit_group;");
    };

    const int NIT = K / BK;           // 64
    issue_stage(0, 0);
    issue_stage(1, BK);
    issue_stage(2, 2 * BK);

    int buf = 0;
    for (int i = 0; i < NIT; i++) {
        if (i + 2 < NIT) {
            asm volatile("cp.async.wait_group 2;");
        } else if (i + 1 < NIT) {
            asm volatile("cp.async.wait_group 1;");
        } else {
            asm volatile("cp.async.wait_group 0;");
        }
        __syncthreads();
        if (i + 3 < NIT) issue_stage((i + 3) & (NSTG - 1), (i + 3) * BK);

        const __half* as = hsm + buf * AWH;
        const __half* bs = hsm + NSTG * AWH + buf * AWH;
#pragma unroll
        for (int kb = 0; kb < BK; kb += 16) {
            uint32_t af[4][4], bf[2][4];
#pragma unroll
            for (int am = 0; am < 4; am++) {
                int row = wm * 64 + am * 16 + (g & 1) * 8 + l8;
                int col = kb + (g >> 1) * 8;
                ldsm4(af[am][0], af[am][1], af[am][2], af[am][3],
                      smem_u32(&as[row * LDH + col]));
            }
#pragma unroll
            for (int ap = 0; ap < 2; ap++) {
                int row = wn * 32 + ap * 16 + (g >> 1) * 8 + l8;
                int col = kb + (g & 1) * 8;
                ldsm4(bf[ap][0], bf[ap][1], bf[ap][2], bf[ap][3],
                      smem_u32(&bs[row * LDH + col]));
            }
#pragma unroll
            for (int am = 0; am < 4; am++)
#pragma unroll
                for (int an = 0; an < 4; an++)
                    mma_f16(acc[am][an], af[am], &bf[an >> 1][(an & 1) * 2]);
        }
        buf = (buf + 1) & (NSTG - 1);
    }

    // ---- epilogue ----
    if (MODE == 0) {
        const int seg = n0 >> 11;           // 0=q, 1=k, 2=v
        const int hh  = (n0 & 2047) >> 7;
#pragma unroll
        for (int am = 0; am < 4; am++) {
#pragma unroll
            for (int cp = 0; cp < 2; cp++) {
                int row = wm * 64 + am * 16 + (lane >> 2) + cp * 8;
                int m = m0 + row;
                int b_ = m >> 11;
                int t  = m & 2047;
                size_t base = (((size_t)(b_ * NH + hh) * T_DIM) + t) * HD;
                if (seg == 0) {
                    __half* dstrow = g_qh + base;
#pragma unroll
                    for (int an = 0; an < 4; an++) {
                        int cl = wn * 32 + an * 8 + (lane & 3) * 2;
                        uint32_t v = pkh(acc[am][an][cp * 2 + 0] + bias[n0 + cl],
                                         acc[am][an][cp * 2 + 1] + bias[n0 + cl + 1]);
                        *reinterpret_cast<uint32_t*>(&dstrow[cl]) = v;
                    }
                } else {
                    float* dstrow = ((seg == 1) ? out0 : out1) + base;
                    __half* hrow  = ((seg == 1) ? g_kh : g_vh) + base;
#pragma unroll
                    for (int an = 0; an < 4; an++) {
                        int cl = wn * 32 + an * 8 + (lane & 3) * 2;
                        float2 v;
                        v.x = acc[am][an][cp * 2 + 0] + bias[n0 + cl];
                        v.y = acc[am][an][cp * 2 + 1] + bias[n0 + cl + 1];
                        *reinterpret_cast<float2*>(&dstrow[cl]) = v;
                        *reinterpret_cast<uint32_t*>(&hrow[cl]) = pkh(v.x, v.y);
                    }
                }
            }
        }
    } else {
#pragma unroll
        for (int am = 0; am < 4; am++) {
#pragma unroll
            for (int cp = 0; cp < 2; cp++) {
                int row = wm * 64 + am * 16 + (lane >> 2) + cp * 8;
                int m = m0 + row;
                float* dstrow = out0 + (size_t)m * C_DIM + n0;
#pragma unroll
                for (int an = 0; an < 4; an++) {
                    int cl = wn * 32 + an * 8 + (lane & 3) * 2;
                    float2 v;
                    v.x = acc[am][an][cp * 2 + 0] + bias[n0 + cl];
                    v.y = acc[am][an][cp * 2 + 1] + bias[n0 + cl + 1];
                    *reinterpret_cast<float2*>(&dstrow[cl]) = v;
                }
            }
        }
    }
}

// ---------------------------------------------------------------------------
// FP16 MMA flash attention: register-P, async double-buffered K/V (.cg),
// heavy-first scheduling, 2 CTAs/SM. BQ=128, BK=64, 256 threads.
// ---------------------------------------------------------------------------
#define ALH 136

__global__ __launch_bounds__(256, 2) void attn_mma_kernel(int dummy)
{
    extern __shared__ __half sh[];
    __half* Qs = sh;                       // 128 x 136
    __half* Ks = Qs + 128 * ALH;           // 2 x 64 x 136
    __half* Vs = Ks + 2 * 64 * ALH;        // 2 x 64 x 136

    const int tid  = threadIdx.x;
    const int lane = tid & 31;
    const int w    = tid >> 5;
    const int g    = lane >> 3;
    const int l8   = lane & 7;
    const int iq   = (int)gridDim.x - 1 - (int)blockIdx.x;  // heavy first
    const int bh   = blockIdx.y;
    const int b    = bh >> 4;
    const int h    = bh & 15;

    const __half* qp = g_qh + ((size_t)bh * T_DIM + iq * 128) * HD;
    const __half* kp = g_kh + (size_t)bh * T_DIM * HD;
    const __half* vp = g_vh + (size_t)bh * T_DIM * HD;

    const int jmax = 2 * iq + 1;

    auto issue_kv = [&](int bufi, int j) {
        const __half* kb = kp + (size_t)j * 64 * HD;
        const __half* vb = vp + (size_t)j * 64 * HD;
        __half* Kd = Ks + bufi * 64 * ALH;
        __half* Vd = Vs + bufi * 64 * ALH;
#pragma unroll
        for (int r = 0; r < 4; r++) {
            int idx = tid + r * 256;
            int row = idx >> 4;
            int c   = (idx & 15) << 3;
            cpasync16(smem_u32(&Kd[row * ALH + c]), &kb[row * HD + c]);
            cpasync16(smem_u32(&Vd[row * ALH + c]), &vb[row * HD + c]);
        }
        asm volatile("cp.async.commit_group;");
    };

    issue_kv(0, 0);

#pragma unroll
    for (int r = 0; r < 8; r++) {
        int idx = tid + r * 256;
        int row = idx >> 4;
        int c   = (idx & 15) << 3;
        *reinterpret_cast<uint4*>(&Qs[row * ALH + c]) =
            *reinterpret_cast<const uint4*>(&qp[row * HD + c]);
    }
    __syncthreads();

    const int r0 = lane >> 2;
    float m_i[2] = {-1e30f, -1e30f};
    float l_i[2] = {0.0f, 0.0f};
    float oacc[16][4];
#pragma unroll
    for (int na = 0; na < 16; na++)
#pragma unroll
        for (int c = 0; c < 4; c++) oacc[na][c] = 0.0f;

    const float scale = 0.08838834764831843f;
    const int qrow_frag = w * 16 + (g & 1) * 8 + l8;

    for (int j = 0; j <= jmax; j++) {
        asm volatile("cp.async.wait_group 0;");
        __syncthreads();
        if (j < jmax) issue_kv((j + 1) & 1, j + 1);

        const __half* Kb = Ks + (j & 1) * 64 * ALH;
        const __half* Vb = Vs + (j & 1) * 64 * ALH;

        float sacc[8][4];
#pragma unroll
        for (int na = 0; na < 8; na++)
#pragma unroll
            for (int c = 0; c < 4; c++) sacc[na][c] = 0.0f;

#pragma unroll
        for (int ks = 0; ks < 8; ks++) {
            uint32_t qf[4];
            {
                int col = ks * 16 + (g >> 1) * 8;
                ldsm4(qf[0], qf[1], qf[2], qf[3],
                      smem_u32(&Qs[qrow_frag * ALH + col]));
            }
#pragma unroll
            for (int np = 0; np < 4; np++) {
                uint32_t bf[4];
                int row = np * 16 + (g >> 1) * 8 + l8;
                int col = ks * 16 + (g & 1) * 8;
                ldsm4(bf[0], bf[1], bf[2], bf[3],
                      smem_u32(&Kb[row * ALH + col]));
                mma_f16(sacc[2 * np],     qf, &bf[0]);
                mma_f16(sacc[2 * np + 1], qf, &bf[2]);
            }
        }

#pragma unroll
        for (int na = 0; na < 8; na++)
#pragma unroll
            for (int c = 0; c < 4; c++) sacc[na][c] *= scale;
        if (j >= 2 * iq) {
            int qrow0 = iq * 128 + w * 16 + r0;
#pragma unroll
            for (int na = 0; na < 8; na++) {
                int col = j * 64 + na * 8 + 2 * (lane & 3);
                if (col > qrow0)         sacc[na][0] = -1e30f;
                if (col + 1 > qrow0)     sacc[na][1] = -1e30f;
                if (col > qrow0 + 8)     sacc[na][2] = -1e30f;
                if (col + 1 > qrow0 + 8) sacc[na][3] = -1e30f;
            }
        }

        float mt[2] = {-1e30f, -1e30f};
#pragma unroll
        for (int na = 0; na < 8; na++) {
            mt[0] = fmaxf(mt[0], fmaxf(sacc[na][0], sacc[na][1]));
            mt[1] = fmaxf(mt[1], fmaxf(sacc[na][2], sacc[na][3]));
        }
#pragma unroll
        for (int off = 1; off <= 2; off <<= 1) {
            mt[0] = fmaxf(mt[0], __shfl_xor_sync(0xffffffffu, mt[0], off));
            mt[1] = fmaxf(mt[1], __shfl_xor_sync(0xffffffffu, mt[1], off));
        }
        float mnew0 = fmaxf(m_i[0], mt[0]);
        float mnew1 = fmaxf(m_i[1], mt[1]);
        float alpha0 = __expf(m_i[0] - mnew0);
        float alpha1 = __expf(m_i[1] - mnew1);
        m_i[0] = mnew0; m_i[1] = mnew1;

        float sum0 = 0.0f, sum1 = 0.0f;
#pragma unroll
        for (int na = 0; na < 8; na++) {
            sacc[na][0] = __expf(sacc[na][0] - mnew0);
            sacc[na][1] = __expf(sacc[na][1] - mnew0);
            sacc[na][2] = __expf(sacc[na][2] - mnew1);
            sacc[na][3] = __expf(sacc[na][3] - mnew1);
            sum0 += sacc[na][0] + sacc[na][1];
            sum1 += sacc[na][2] + sacc[na][3];
        }
#pragma unroll
        for (int off = 1; off <= 2; off <<= 1) {
            sum0 += __shfl_xor_sync(0xffffffffu, sum0, off);
            sum1 += __shfl_xor_sync(0xffffffffu, sum1, off);
        }
        l_i[0] = l_i[0] * alpha0 + sum0;
        l_i[1] = l_i[1] * alpha1 + sum1;
#pragma unroll
        for (int na = 0; na < 16; na++) {
            oacc[na][0] *= alpha0; oacc[na][1] *= alpha0;
            oacc[na][2] *= alpha1; oacc[na][3] *= alpha1;
        }

#pragma unroll
        for (int kc = 0; kc < 4; kc++) {
            uint32_t pa[4];
            pa[0] = pkh(sacc[2 * kc][0],     sacc[2 * kc][1]);
            pa[1] = pkh(sacc[2 * kc][2],     sacc[2 * kc][3]);
            pa[2] = pkh(sacc[2 * kc + 1][0], sacc[2 * kc + 1][1]);
            pa[3] = pkh(sacc[2 * kc + 1][2], sacc[2 * kc + 1][3]);
#pragma unroll
            for (int ng = 0; ng < 8; ng++) {
                uint32_t vf[4];
                int row = kc * 16 + (g & 1) * 8 + l8;
                int col = ng * 16 + (g >> 1) * 8;
                ldsm4t(vf[0], vf[1], vf[2], vf[3],
                       smem_u32(&Vb[row * ALH + col]));
                mma_f16(oacc[2 * ng],     pa, &vf[0]);
                mma_f16(oacc[2 * ng + 1], pa, &vf[2]);
            }
        }
    }

    float inv0 = 1.0f / l_i[0];
    float inv1 = 1.0f / l_i[1];
    int t0 = iq * 128 + w * 16 + r0;
    int t1 = t0 + 8;
    __half* dst0 = g_yh + ((size_t)(b * T_DIM + t0) * C_DIM) + h * HD;
    __half* dst1 = g_yh + ((size_t)(b * T_DIM + t1) * C_DIM) + h * HD;
#pragma unroll
    for (int na = 0; na < 16; na++) {
        int col = na * 8 + 2 * (lane & 3);
        *reinterpret_cast<uint32_t*>(&dst0[col]) =
            pkh(oacc[na][0] * inv0, oacc[na][1] * inv0);
        *reinterpret_cast<uint32_t*>(&dst1[col]) =
            pkh(oacc[na][2] * inv1, oacc[na][3] * inv1);
    }
}

// ---------------------------------------------------------------------------
extern "C" void kernel_launch(void* const* d_in, const int* in_sizes, int n_in,
                              void* d_out, int out_size)
{
    const float* x    = (const float*)d_in[0];
    const float* Wqkv = (const float*)d_in[1];
    const float* bqkv = (const float*)d_in[2];
    const float* Wout = (const float*)d_in[3];
    const float* bout = (const float*)d_in[4];

    float* y    = (float*)d_out;
    float* kout = y + YELEMS;
    float* vout = y + 2 * YELEMS;

    __half *xh, *wqkvh, *wouth, *yh;
    cudaGetSymbolAddress((void**)&xh,    g_xh);
    cudaGetSymbolAddress((void**)&wqkvh, g_wqkvh);
    cudaGetSymbolAddress((void**)&wouth, g_wouth);
    cudaGetSymbolAddress((void**)&yh,    g_yh);

    const int attn_smem = (128 + 128 + 128) * ALH * 2;   // 104448
    cudaFuncSetAttribute(attn_mma_kernel,
                         cudaFuncAttributeMaxDynamicSharedMemorySize, attn_smem);
    cudaFuncSetAttribute(mma_gemm<0>,
                         cudaFuncAttributeMaxDynamicSharedMemorySize, GEMM_SMEM);
    cudaFuncSetAttribute(mma_gemm<1>,
                         cudaFuncAttributeMaxDynamicSharedMemorySize, GEMM_SMEM);

    // 0) fp16 pre-conversion (single launch)
    cvt_all_kernel<<<8192, 256>>>((const float4*)x, (uint2*)xh,
                                  (const float4*)Wqkv, (uint2*)wqkvh,
                                  (const float4*)Wout, (uint2*)wouth);

    // 1) QKV projection (fp16 MMA, 4-stage .cg ring, swizzled 1D grid)
    mma_gemm<0><<<(3 * C_DIM / BN) * (MTOT / BM), 256, GEMM_SMEM>>>(
        xh, wqkvh, bqkv, kout, vout);

    // 2) causal flash attention (register P, async K/V, 2 CTA/SM) -> g_yh
    attn_mma_kernel<<<dim3(T_DIM / 128, B_DIM * NH), 256, attn_smem>>>(0);

    // 3) output projection -> y (swizzled 1D grid)
    mma_gemm<1><<<(C_DIM / BN) * (MTOT / BM), 256, GEMM_SMEM>>>(
        yh, wouth, bout, y, nullptr);
}

// round 16
// speedup vs baseline: 1.2370x; 1.0008x over previous
#include <cuda_runtime.h>
#include <cuda_fp16.h>
#include <cstdint>

// Shapes (fixed): B=4, T=2048, C=2048, nH=16, hd=128
// Output = concat(y [B,T,C], new_k [B,nH,T,hd], new_v [B,nH,T,hd])

#define C_DIM   2048
#define T_DIM   2048
#define B_DIM   4
#define NH      16
#define HD      128
#define MTOT    (B_DIM * T_DIM)         // 8192
#define YELEMS  (B_DIM * T_DIM * C_DIM) // 16777216

// fp16 staging buffers
__device__ __half g_xh[YELEMS];
__device__ __half g_wqkvh[3 * C_DIM * C_DIM];
__device__ __half g_wouth[C_DIM * C_DIM];
__device__ __half g_qh[YELEMS];     // q [B,nH,T,hd]  (pre-scaled by 1/sqrt(hd))
__device__ __half g_kh[YELEMS];     // k fp16 copy for attn
__device__ __half g_vh[YELEMS];     // v fp16 copy for attn
__device__ __half g_yh[YELEMS];     // attn out [B,T,C]

__device__ __forceinline__ uint32_t pkh(float lo, float hi) {
    __half2 h = __floats2half2_rn(lo, hi);
    return *reinterpret_cast<uint32_t*>(&h);
}

__device__ __forceinline__ void mma_f16(float* c, const uint32_t* a,
                                        const uint32_t* b) {
    asm volatile(
        "mma.sync.aligned.m16n8k16.row.col.f32.f16.f16.f32 "
        "{%0,%1,%2,%3},{%4,%5,%6,%7},{%8,%9},{%0,%1,%2,%3};"
        : "+f"(c[0]), "+f"(c[1]), "+f"(c[2]), "+f"(c[3])
        : "r"(a[0]), "r"(a[1]), "r"(a[2]), "r"(a[3]), "r"(b[0]), "r"(b[1]));
}

__device__ __forceinline__ void ldsm4(uint32_t& r0, uint32_t& r1,
                                      uint32_t& r2, uint32_t& r3, uint32_t a) {
    asm volatile("ldmatrix.sync.aligned.m8n8.x4.shared.b16 {%0,%1,%2,%3},[%4];"
                 : "=r"(r0), "=r"(r1), "=r"(r2), "=r"(r3) : "r"(a));
}
__device__ __forceinline__ void ldsm4t(uint32_t& r0, uint32_t& r1,
                                       uint32_t& r2, uint32_t& r3, uint32_t a) {
    asm volatile(
        "ldmatrix.sync.aligned.m8n8.x4.trans.shared.b16 {%0,%1,%2,%3},[%4];"
        : "=r"(r0), "=r"(r1), "=r"(r2), "=r"(r3) : "r"(a));
}

// .cg: bypass L1 — L1/shared bandwidth belongs to ldmatrix (R13 lesson)
__device__ __forceinline__ void cpasync16(uint32_t smem_addr, const void* g) {
    asm volatile("cp.async.cg.shared.global [%0], [%1], 16;"
                 :: "r"(smem_addr), "l"(g));
}

__device__ __forceinline__ uint32_t smem_u32(const void* p) {
    return (uint32_t)__cvta_generic_to_shared(p);
}

// ---------------------------------------------------------------------------
// fp32 -> fp16 conversion, all three tensors in ONE launch
// ---------------------------------------------------------------------------
#define N4_X   (YELEMS / 4)                    // 4194304
#define N4_WQ  (3 * C_DIM * C_DIM / 4)         // 3145728
#define N4_WO  (C_DIM * C_DIM / 4)             // 1048576

__global__ __launch_bounds__(256) void cvt_all_kernel(
    const float4* __restrict__ x,  uint2* __restrict__ xh,
    const float4* __restrict__ wq, uint2* __restrict__ wqh,
    const float4* __restrict__ wo, uint2* __restrict__ woh)
{
    const int total = N4_X + N4_WQ + N4_WO;
    for (int i = blockIdx.x * blockDim.x + threadIdx.x; i < total;
         i += gridDim.x * blockDim.x) {
        const float4* s;
        uint2* d;
        int idx;
        if (i < N4_X)              { s = x;  d = xh;  idx = i; }
        else if (i < N4_X + N4_WQ) { s = wq; d = wqh; idx = i - N4_X; }
        else                       { s = wo; d = woh; idx = i - N4_X - N4_WQ; }
        float4 v = s[idx];
        uint2 o;
        o.x = pkh(v.x, v.y);
        o.y = pkh(v.z, v.w);
        d[idx] = o;
    }
}

// ---------------------------------------------------------------------------
// FP16 GEMM (R14-proven): 128x128x32, 256 threads, warp 64x32, m16n8k16.
// 4-stage cp.async ring (.cg), one barrier/iter, 2 CTAs/SM.
// GROUP_M=16 L2 grid swizzle on a 1D grid.
// ---------------------------------------------------------------------------
#define BM 128
#define BN 128
#define BK 32
#define LDH 40
#define AWH (BM * LDH)                 // 5120 halves / stage / matrix
#define NSTG 4
#define GEMM_SMEM (2 * NSTG * AWH * 2) // 81920 B
#define GROUP_M 16

#define QK_SCALE 0.08838834764831843f  // 1/sqrt(128)

template <int MODE>
__global__ __launch_bounds__(256, 2) void mma_gemm(
    const __half* __restrict__ A,     // [M,2048]
    const __half* __restrict__ W,     // [N,2048]
    const float* __restrict__ bias,
    float* __restrict__ out0,         // MODE0: k ; MODE1: y
    float* __restrict__ out1)         // MODE0: v
{
    const int K = C_DIM;
    extern __shared__ __half hsm[];

    // --- L2 grid swizzle ---
    constexpr int NPN = (MODE == 0) ? (3 * C_DIM / BN) : (C_DIM / BN);
    const int bid        = blockIdx.x;
    const int group_size = GROUP_M * NPN;
    const int group_id   = bid / group_size;
    const int pid_in     = bid % group_size;
    const int pid_m      = group_id * GROUP_M + (pid_in % GROUP_M);
    const int pid_n      = pid_in / GROUP_M;
    const int m0         = pid_m * BM;
    const int n0         = pid_n * BN;

    const int tid  = threadIdx.x;
    const int lane = tid & 31;
    const int wid  = tid >> 5;
    const int wm   = wid >> 2;        // 0..1
    const int wn   = wid & 3;         // 0..3

    const int g   = lane >> 3;
    const int l8  = lane & 7;

    const int crow = tid >> 2;        // 0..63
    const int ckq  = (tid & 3) << 3;  // 0,8,16,24 halves

    float acc[4][4][4];
#pragma unroll
    for (int i = 0; i < 4; i++)
#pragma unroll
        for (int j = 0; j < 4; j++)
#pragma unroll
            for (int c = 0; c < 4; c++) acc[i][j][c] = 0.0f;

    auto issue_stage = [&](int s, int k0) {
        __half* as = hsm + s * AWH;
        __half* bs = hsm + NSTG * AWH + s * AWH;
#pragma unroll
        for (int r = 0; r < 2; r++) {
            int row = crow + r * 64;
            cpasync16(smem_u32(&as[row * LDH + ckq]),
                      &A[(size_t)(m0 + row) * K + k0 + ckq]);
            cpasync16(smem_u32(&bs[row * LDH + ckq]),
                      &W[(size_t)(n0 + row) * K + k0 + ckq]);
        }
        asm volatile("cp.async.commit_group;");
    };

    const int NIT = K / BK;           // 64
    issue_stage(0, 0);
    issue_stage(1, BK);
    issue_stage(2, 2 * BK);

    int buf = 0;
    for (int i = 0; i < NIT; i++) {
        if (i + 2 < NIT) {
            asm volatile("cp.async.wait_group 2;");
        } else if (i + 1 < NIT) {
            asm volatile("cp.async.wait_group 1;");
        } else {
            asm volatile("cp.async.wait_group 0;");
        }
        __syncthreads();
        if (i + 3 < NIT) issue_stage((i + 3) & (NSTG - 1), (i + 3) * BK);

        const __half* as = hsm + buf * AWH;
        const __half* bs = hsm + NSTG * AWH + buf * AWH;
#pragma unroll
        for (int kb = 0; kb < BK; kb += 16) {
            uint32_t af[4][4], bf[2][4];
#pragma unroll
            for (int am = 0; am < 4; am++) {
                int row = wm * 64 + am * 16 + (g & 1) * 8 + l8;
                int col = kb + (g >> 1) * 8;
                ldsm4(af[am][0], af[am][1], af[am][2], af[am][3],
                      smem_u32(&as[row * LDH + col]));
            }
#pragma unroll
            for (int ap = 0; ap < 2; ap++) {
                int row = wn * 32 + ap * 16 + (g >> 1) * 8 + l8;
                int col = kb + (g & 1) * 8;
                ldsm4(bf[ap][0], bf[ap][1], bf[ap][2], bf[ap][3],
                      smem_u32(&bs[row * LDH + col]));
            }
#pragma unroll
            for (int am = 0; am < 4; am++)
#pragma unroll
                for (int an = 0; an < 4; an++)
                    mma_f16(acc[am][an], af[am], &bf[an >> 1][(an & 1) * 2]);
        }
        buf = (buf + 1) & (NSTG - 1);
    }

    // ---- epilogue ----
    if (MODE == 0) {
        const int seg = n0 >> 11;           // 0=q, 1=k, 2=v
        const int hh  = (n0 & 2047) >> 7;
#pragma unroll
        for (int am = 0; am < 4; am++) {
#pragma unroll
            for (int cp = 0; cp < 2; cp++) {
                int row = wm * 64 + am * 16 + (lane >> 2) + cp * 8;
                int m = m0 + row;
                int b_ = m >> 11;
                int t  = m & 2047;
                size_t base = (((size_t)(b_ * NH + hh) * T_DIM) + t) * HD;
                if (seg == 0) {
                    __half* dstrow = g_qh + base;
#pragma unroll
                    for (int an = 0; an < 4; an++) {
                        int cl = wn * 32 + an * 8 + (lane & 3) * 2;
                        // fold softmax scale into q here (consumed only by QK^T)
                        uint32_t v = pkh(
                            (acc[am][an][cp * 2 + 0] + bias[n0 + cl]) * QK_SCALE,
                            (acc[am][an][cp * 2 + 1] + bias[n0 + cl + 1]) * QK_SCALE);
                        *reinterpret_cast<uint32_t*>(&dstrow[cl]) = v;
                    }
                } else {
                    float* dstrow = ((seg == 1) ? out0 : out1) + base;
                    __half* hrow  = ((seg == 1) ? g_kh : g_vh) + base;
#pragma unroll
                    for (int an = 0; an < 4; an++) {
                        int cl = wn * 32 + an * 8 + (lane & 3) * 2;
                        float2 v;
                        v.x = acc[am][an][cp * 2 + 0] + bias[n0 + cl];
                        v.y = acc[am][an][cp * 2 + 1] + bias[n0 + cl + 1];
                        *reinterpret_cast<float2*>(&dstrow[cl]) = v;
                        *reinterpret_cast<uint32_t*>(&hrow[cl]) = pkh(v.x, v.y);
                    }
                }
            }
        }
    } else {
#pragma unroll
        for (int am = 0; am < 4; am++) {
#pragma unroll
            for (int cp = 0; cp < 2; cp++) {
                int row = wm * 64 + am * 16 + (lane >> 2) + cp * 8;
                int m = m0 + row;
                float* dstrow = out0 + (size_t)m * C_DIM + n0;
#pragma unroll
                for (int an = 0; an < 4; an++) {
                    int cl = wn * 32 + an * 8 + (lane & 3) * 2;
                    float2 v;
                    v.x = acc[am][an][cp * 2 + 0] + bias[n0 + cl];
                    v.y = acc[am][an][cp * 2 + 1] + bias[n0 + cl + 1];
                    *reinterpret_cast<float2*>(&dstrow[cl]) = v;
                }
            }
        }
    }
}

// ---------------------------------------------------------------------------
// FP16 MMA flash attention: register-P, async double-buffered K/V (.cg),
// heavy-first scheduling, 2 CTAs/SM. BQ=128, BK=64, 256 threads.
// q arrives pre-scaled, so S needs no per-element scale.
// ---------------------------------------------------------------------------
#define ALH 136

__global__ __launch_bounds__(256, 2) void attn_mma_kernel(int dummy)
{
    extern __shared__ __half sh[];
    __half* Qs = sh;                       // 128 x 136
    __half* Ks = Qs + 128 * ALH;           // 2 x 64 x 136
    __half* Vs = Ks + 2 * 64 * ALH;        // 2 x 64 x 136

    const int tid  = threadIdx.x;
    const int lane = tid & 31;
    const int w    = tid >> 5;
    const int g    = lane >> 3;
    const int l8   = lane & 7;
    const int iq   = (int)gridDim.x - 1 - (int)blockIdx.x;  // heavy first
    const int bh   = blockIdx.y;
    const int b    = bh >> 4;
    const int h    = bh & 15;

    const __half* qp = g_qh + ((size_t)bh * T_DIM + iq * 128) * HD;
    const __half* kp = g_kh + (size_t)bh * T_DIM * HD;
    const __half* vp = g_vh + (size_t)bh * T_DIM * HD;

    const int jmax = 2 * iq + 1;

    auto issue_kv = [&](int bufi, int j) {
        const __half* kb = kp + (size_t)j * 64 * HD;
        const __half* vb = vp + (size_t)j * 64 * HD;
        __half* Kd = Ks + bufi * 64 * ALH;
        __half* Vd = Vs + bufi * 64 * ALH;
#pragma unroll
        for (int r = 0; r < 4; r++) {
            int idx = tid + r * 256;
            int row = idx >> 4;
            int c   = (idx & 15) << 3;
            cpasync16(smem_u32(&Kd[row * ALH + c]), &kb[row * HD + c]);
            cpasync16(smem_u32(&Vd[row * ALH + c]), &vb[row * HD + c]);
        }
        asm volatile("cp.async.commit_group;");
    };

    issue_kv(0, 0);

#pragma unroll
    for (int r = 0; r < 8; r++) {
        int idx = tid + r * 256;
        int row = idx >> 4;
        int c   = (idx & 15) << 3;
        *reinterpret_cast<uint4*>(&Qs[row * ALH + c]) =
            *reinterpret_cast<const uint4*>(&qp[row * HD + c]);
    }
    __syncthreads();

    const int r0 = lane >> 2;
    float m_i[2] = {-1e30f, -1e30f};
    float l_i[2] = {0.0f, 0.0f};
    float oacc[16][4];
#pragma unroll
    for (int na = 0; na < 16; na++)
#pragma unroll
        for (int c = 0; c < 4; c++) oacc[na][c] = 0.0f;

    const int qrow_frag = w * 16 + (g & 1) * 8 + l8;

    for (int j = 0; j <= jmax; j++) {
        asm volatile("cp.async.wait_group 0;");
        __syncthreads();
        if (j < jmax) issue_kv((j + 1) & 1, j + 1);

        const __half* Kb = Ks + (j & 1) * 64 * ALH;
        const __half* Vb = Vs + (j & 1) * 64 * ALH;

        float sacc[8][4];
#pragma unroll
        for (int na = 0; na < 8; na++)
#pragma unroll
            for (int c = 0; c < 4; c++) sacc[na][c] = 0.0f;

#pragma unroll
        for (int ks = 0; ks < 8; ks++) {
            uint32_t qf[4];
            {
                int col = ks * 16 + (g >> 1) * 8;
                ldsm4(qf[0], qf[1], qf[2], qf[3],
                      smem_u32(&Qs[qrow_frag * ALH + col]));
            }
#pragma unroll
            for (int np = 0; np < 4; np++) {
                uint32_t bf[4];
                int row = np * 16 + (g >> 1) * 8 + l8;
                int col = ks * 16 + (g & 1) * 8;
                ldsm4(bf[0], bf[1], bf[2], bf[3],
                      smem_u32(&Kb[row * ALH + col]));
                mma_f16(sacc[2 * np],     qf, &bf[0]);
                mma_f16(sacc[2 * np + 1], qf, &bf[2]);
            }
        }

        // causal mask (q pre-scaled; no scale pass needed)
        if (j >= 2 * iq) {
            int qrow0 = iq * 128 + w * 16 + r0;
#pragma unroll
            for (int na = 0; na < 8; na++) {
                int col = j * 64 + na * 8 + 2 * (lane & 3);
                if (col > qrow0)         sacc[na][0] = -1e30f;
                if (col + 1 > qrow0)     sacc[na][1] = -1e30f;
                if (col > qrow0 + 8)     sacc[na][2] = -1e30f;
                if (col + 1 > qrow0 + 8) sacc[na][3] = -1e30f;
            }
        }

        float mt[2] = {-1e30f, -1e30f};
#pragma unroll
        for (int na = 0; na < 8; na++) {
            mt[0] = fmaxf(mt[0], fmaxf(sacc[na][0], sacc[na][1]));
            mt[1] = fmaxf(mt[1], fmaxf(sacc[na][2], sacc[na][3]));
        }
#pragma unroll
        for (int off = 1; off <= 2; off <<= 1) {
            mt[0] = fmaxf(mt[0], __shfl_xor_sync(0xffffffffu, mt[0], off));
            mt[1] = fmaxf(mt[1], __shfl_xor_sync(0xffffffffu, mt[1], off));
        }
        float mnew0 = fmaxf(m_i[0], mt[0]);
        float mnew1 = fmaxf(m_i[1], mt[1]);
        float alpha0 = __expf(m_i[0] - mnew0);
        float alpha1 = __expf(m_i[1] - mnew1);
        m_i[0] = mnew0; m_i[1] = mnew1;

        float sum0 = 0.0f, sum1 = 0.0f;
#pragma unroll
        for (int na = 0; na < 8; na++) {
            sacc[na][0] = __expf(sacc[na][0] - mnew0);
            sacc[na][1] = __expf(sacc[na][1] - mnew0);
            sacc[na][2] = __expf(sacc[na][2] - mnew1);
            sacc[na][3] = __expf(sacc[na][3] - mnew1);
            sum0 += sacc[na][0] + sacc[na][1];
            sum1 += sacc[na][2] + sacc[na][3];
        }
#pragma unroll
        for (int off = 1; off <= 2; off <<= 1) {
            sum0 += __shfl_xor_sync(0xffffffffu, sum0, off);
            sum1 += __shfl_xor_sync(0xffffffffu, sum1, off);
        }
        l_i[0] = l_i[0] * alpha0 + sum0;
        l_i[1] = l_i[1] * alpha1 + sum1;
#pragma unroll
        for (int na = 0; na < 16; na++) {
            oacc[na][0] *= alpha0; oacc[na][1] *= alpha0;
            oacc[na][2] *= alpha1; oacc[na][3] *= alpha1;
        }

#pragma unroll
        for (int kc = 0; kc < 4; kc++) {
            uint32_t pa[4];
            pa[0] = pkh(sacc[2 * kc][0],     sacc[2 * kc][1]);
            pa[1] = pkh(sacc[2 * kc][2],     sacc[2 * kc][3]);
            pa[2] = pkh(sacc[2 * kc + 1][0], sacc[2 * kc + 1][1]);
            pa[3] = pkh(sacc[2 * kc + 1][2], sacc[2 * kc + 1][3]);
#pragma unroll
            for (int ng = 0; ng < 8; ng++) {
                uint32_t vf[4];
                int row = kc * 16 + (g & 1) * 8 + l8;
                int col = ng * 16 + (g >> 1) * 8;
                ldsm4t(vf[0], vf[1], vf[2], vf[3],
                       smem_u32(&Vb[row * ALH + col]));
                mma_f16(oacc[2 * ng],     pa, &vf[0]);
                mma_f16(oacc[2 * ng + 1], pa, &vf[2]);
            }
        }
    }

    float inv0 = 1.0f / l_i[0];
    float inv1 = 1.0f / l_i[1];
    int t0 = iq * 128 + w * 16 + r0;
    int t1 = t0 + 8;
    __half* dst0 = g_yh + ((size_t)(b * T_DIM + t0) * C_DIM) + h * HD;
    __half* dst1 = g_yh + ((size_t)(b * T_DIM + t1) * C_DIM) + h * HD;
#pragma unroll
    for (int na = 0; na < 16; na++) {
        int col = na * 8 + 2 * (lane & 3);
        *reinterpret_cast<uint32_t*>(&dst0[col]) =
            pkh(oacc[na][0] * inv0, oacc[na][1] * inv0);
        *reinterpret_cast<uint32_t*>(&dst1[col]) =
            pkh(oacc[na][2] * inv1, oacc[na][3] * inv1);
    }
}

// ---------------------------------------------------------------------------
extern "C" void kernel_launch(void* const* d_in, const int* in_sizes, int n_in,
                              void* d_out, int out_size)
{
    const float* x    = (const float*)d_in[0];
    const float* Wqkv = (const float*)d_in[1];
    const float* bqkv = (const float*)d_in[2];
    const float* Wout = (const float*)d_in[3];
    const float* bout = (const float*)d_in[4];

    float* y    = (float*)d_out;
    float* kout = y + YELEMS;
    float* vout = y + 2 * YELEMS;

    __half *xh, *wqkvh, *wouth, *yh;
    cudaGetSymbolAddress((void**)&xh,    g_xh);
    cudaGetSymbolAddress((void**)&wqkvh, g_wqkvh);
    cudaGetSymbolAddress((void**)&wouth, g_wouth);
    cudaGetSymbolAddress((void**)&yh,    g_yh);

    const int attn_smem = (128 + 128 + 128) * ALH * 2;   // 104448
    cudaFuncSetAttribute(attn_mma_kernel,
                         cudaFuncAttributeMaxDynamicSharedMemorySize, attn_smem);
    cudaFuncSetAttribute(mma_gemm<0>,
                         cudaFuncAttributeMaxDynamicSharedMemorySize, GEMM_SMEM);
    cudaFuncSetAttribute(mma_gemm<1>,
                         cudaFuncAttributeMaxDynamicSharedMemorySize, GEMM_SMEM);

    // 0) fp16 pre-conversion (single launch)
    cvt_all_kernel<<<8192, 256>>>((const float4*)x, (uint2*)xh,
                                  (const float4*)Wqkv, (uint2*)wqkvh,
                                  (const float4*)Wout, (uint2*)wouth);

    // 1) QKV projection (fp16 MMA, 4-stage .cg ring, swizzled 1D grid)
    mma_gemm<0><<<(3 * C_DIM / BN) * (MTOT / BM), 256, GEMM_SMEM>>>(
        xh, wqkvh, bqkv, kout, vout);

    // 2) causal flash attention (register P, async K/V, 2 CTA/SM) -> g_yh
    attn_mma_kernel<<<dim3(T_DIM / 128, B_DIM * NH), 256, attn_smem>>>(0);

    // 3) output projection -> y (swizzled 1D grid)
    mma_gemm<1><<<(C_DIM / BN) * (MTOT / BM), 256, GEMM_SMEM>>>(
        yh, wouth, bout, y, nullptr);
}

// round 17
// speedup vs baseline: 1.2388x; 1.0014x over previous
#include <cuda_runtime.h>
#include <cuda_fp16.h>
#include <cstdint>

// Shapes (fixed): B=4, T=2048, C=2048, nH=16, hd=128
// Output = concat(y [B,T,C], new_k [B,nH,T,hd], new_v [B,nH,T,hd])

#define C_DIM   2048
#define T_DIM   2048
#define B_DIM   4
#define NH      16
#define HD      128
#define MTOT    (B_DIM * T_DIM)         // 8192
#define YELEMS  (B_DIM * T_DIM * C_DIM) // 16777216

// fp16 staging buffers
__device__ __half g_xh[YELEMS];
__device__ __half g_wqkvh[3 * C_DIM * C_DIM];
__device__ __half g_wouth[C_DIM * C_DIM];
__device__ __half g_qh[YELEMS];     // q [B,nH,T,hd]  (pre-scaled by 1/sqrt(hd))
__device__ __half g_kh[YELEMS];     // k fp16 copy for attn
__device__ __half g_vh[YELEMS];     // v fp16 copy for attn
__device__ __half g_yh[YELEMS];     // attn out [B,T,C]

__device__ __forceinline__ uint32_t pkh(float lo, float hi) {
    __half2 h = __floats2half2_rn(lo, hi);
    return *reinterpret_cast<uint32_t*>(&h);
}

__device__ __forceinline__ void mma_f16(float* c, const uint32_t* a,
                                        const uint32_t* b) {
    asm volatile(
        "mma.sync.aligned.m16n8k16.row.col.f32.f16.f16.f32 "
        "{%0,%1,%2,%3},{%4,%5,%6,%7},{%8,%9},{%0,%1,%2,%3};"
        : "+f"(c[0]), "+f"(c[1]), "+f"(c[2]), "+f"(c[3])
        : "r"(a[0]), "r"(a[1]), "r"(a[2]), "r"(a[3]), "r"(b[0]), "r"(b[1]));
}

__device__ __forceinline__ void ldsm4(uint32_t& r0, uint32_t& r1,
                                      uint32_t& r2, uint32_t& r3, uint32_t a) {
    asm volatile("ldmatrix.sync.aligned.m8n8.x4.shared.b16 {%0,%1,%2,%3},[%4];"
                 : "=r"(r0), "=r"(r1), "=r"(r2), "=r"(r3) : "r"(a));
}
__device__ __forceinline__ void ldsm4t(uint32_t& r0, uint32_t& r1,
                                       uint32_t& r2, uint32_t& r3, uint32_t a) {
    asm volatile(
        "ldmatrix.sync.aligned.m8n8.x4.trans.shared.b16 {%0,%1,%2,%3},[%4];"
        : "=r"(r0), "=r"(r1), "=r"(r2), "=r"(r3) : "r"(a));
}

// .cg: bypass L1 — L1/shared bandwidth belongs to ldmatrix (R13 lesson)
__device__ __forceinline__ void cpasync16(uint32_t smem_addr, const void* g) {
    asm volatile("cp.async.cg.shared.global [%0], [%1], 16;"
                 :: "r"(smem_addr), "l"(g));
}

__device__ __forceinline__ uint32_t smem_u32(const void* p) {
    return (uint32_t)__cvta_generic_to_shared(p);
}

// ---------------------------------------------------------------------------
// fp32 -> fp16 conversion, statically partitioned grid (no per-iter branch)
// blocks [0,4096): x ; [4096,7168): Wqkv ; [7168,8192): Wout
// ---------------------------------------------------------------------------
#define N4_X   (YELEMS / 4)                    // 4194304
#define N4_WQ  (3 * C_DIM * C_DIM / 4)         // 3145728
#define N4_WO  (C_DIM * C_DIM / 4)             // 1048576
#define CVT_BX 4096
#define CVT_BQ 3072
#define CVT_BO 1024
#define CVT_GRID (CVT_BX + CVT_BQ + CVT_BO)    // 8192

__global__ __launch_bounds__(256) void cvt_all_kernel(
    const float4* __restrict__ x,  uint2* __restrict__ xh,
    const float4* __restrict__ wq, uint2* __restrict__ wqh,
    const float4* __restrict__ wo, uint2* __restrict__ woh)
{
    const float4* s;
    uint2* d;
    int n4, base;
    if (blockIdx.x < CVT_BX) {
        s = x;  d = xh;  n4 = N4_X;  base = blockIdx.x;
        for (int i = base * 256 + threadIdx.x; i < n4; i += CVT_BX * 256) {
            float4 v = s[i];
            uint2 o; o.x = pkh(v.x, v.y); o.y = pkh(v.z, v.w);
            d[i] = o;
        }
    } else if (blockIdx.x < CVT_BX + CVT_BQ) {
        s = wq; d = wqh; n4 = N4_WQ; base = blockIdx.x - CVT_BX;
        for (int i = base * 256 + threadIdx.x; i < n4; i += CVT_BQ * 256) {
            float4 v = s[i];
            uint2 o; o.x = pkh(v.x, v.y); o.y = pkh(v.z, v.w);
            d[i] = o;
        }
    } else {
        s = wo; d = woh; n4 = N4_WO; base = blockIdx.x - CVT_BX - CVT_BQ;
        for (int i = base * 256 + threadIdx.x; i < n4; i += CVT_BO * 256) {
            float4 v = s[i];
            uint2 o; o.x = pkh(v.x, v.y); o.y = pkh(v.z, v.w);
            d[i] = o;
        }
    }
}

// ---------------------------------------------------------------------------
// FP16 GEMM (R14/R16-proven): 128x128x32, 256 threads, warp 64x32, m16n8k16.
// 4-stage cp.async ring (.cg), one barrier/iter, 2 CTAs/SM.
// GROUP_M=16 L2 grid swizzle on a 1D grid.
// ---------------------------------------------------------------------------
#define BM 128
#define BN 128
#define BK 32
#define LDH 40
#define AWH (BM * LDH)                 // 5120 halves / stage / matrix
#define NSTG 4
#define GEMM_SMEM (2 * NSTG * AWH * 2) // 81920 B
#define GROUP_M 16

#define QK_SCALE 0.08838834764831843f  // 1/sqrt(128)

template <int MODE>
__global__ __launch_bounds__(256, 2) void mma_gemm(
    const __half* __restrict__ A,     // [M,2048]
    const __half* __restrict__ W,     // [N,2048]
    const float* __restrict__ bias,
    float* __restrict__ out0,         // MODE0: k ; MODE1: y
    float* __restrict__ out1)         // MODE0: v
{
    const int K = C_DIM;
    extern __shared__ __half hsm[];

    // --- L2 grid swizzle ---
    constexpr int NPN = (MODE == 0) ? (3 * C_DIM / BN) : (C_DIM / BN);
    const int bid        = blockIdx.x;
    const int group_size = GROUP_M * NPN;
    const int group_id   = bid / group_size;
    const int pid_in     = bid % group_size;
    const int pid_m      = group_id * GROUP_M + (pid_in % GROUP_M);
    const int pid_n      = pid_in / GROUP_M;
    const int m0         = pid_m * BM;
    const int n0         = pid_n * BN;

    const int tid  = threadIdx.x;
    const int lane = tid & 31;
    const int wid  = tid >> 5;
    const int wm   = wid >> 2;        // 0..1
    const int wn   = wid & 3;         // 0..3

    const int g   = lane >> 3;
    const int l8  = lane & 7;

    const int crow = tid >> 2;        // 0..63
    const int ckq  = (tid & 3) << 3;  // 0,8,16,24 halves

    float acc[4][4][4];
#pragma unroll
    for (int i = 0; i < 4; i++)
#pragma unroll
        for (int j = 0; j < 4; j++)
#pragma unroll
            for (int c = 0; c < 4; c++) acc[i][j][c] = 0.0f;

    auto issue_stage = [&](int s, int k0) {
        __half* as = hsm + s * AWH;
        __half* bs = hsm + NSTG * AWH + s * AWH;
#pragma unroll
        for (int r = 0; r < 2; r++) {
            int row = crow + r * 64;
            cpasync16(smem_u32(&as[row * LDH + ckq]),
                      &A[(size_t)(m0 + row) * K + k0 + ckq]);
            cpasync16(smem_u32(&bs[row * LDH + ckq]),
                      &W[(size_t)(n0 + row) * K + k0 + ckq]);
        }
        asm volatile("cp.async.commit_group;");
    };

    const int NIT = K / BK;           // 64
    issue_stage(0, 0);
    issue_stage(1, BK);
    issue_stage(2, 2 * BK);

    int buf = 0;
    for (int i = 0; i < NIT; i++) {
        if (i + 2 < NIT) {
            asm volatile("cp.async.wait_group 2;");
        } else if (i + 1 < NIT) {
            asm volatile("cp.async.wait_group 1;");
        } else {
            asm volatile("cp.async.wait_group 0;");
        }
        __syncthreads();
        if (i + 3 < NIT) issue_stage((i + 3) & (NSTG - 1), (i + 3) * BK);

        const __half* as = hsm + buf * AWH;
        const __half* bs = hsm + NSTG * AWH + buf * AWH;
#pragma unroll
        for (int kb = 0; kb < BK; kb += 16) {
            uint32_t af[4][4], bf[2][4];
#pragma unroll
            for (int am = 0; am < 4; am++) {
                int row = wm * 64 + am * 16 + (g & 1) * 8 + l8;
                int col = kb + (g >> 1) * 8;
                ldsm4(af[am][0], af[am][1], af[am][2], af[am][3],
                      smem_u32(&as[row * LDH + col]));
            }
#pragma unroll
            for (int ap = 0; ap < 2; ap++) {
                int row = wn * 32 + ap * 16 + (g >> 1) * 8 + l8;
                int col = kb + (g & 1) * 8;
                ldsm4(bf[ap][0], bf[ap][1], bf[ap][2], bf[ap][3],
                      smem_u32(&bs[row * LDH + col]));
            }
#pragma unroll
            for (int am = 0; am < 4; am++)
#pragma unroll
                for (int an = 0; an < 4; an++)
                    mma_f16(acc[am][an], af[am], &bf[an >> 1][(an & 1) * 2]);
        }
        buf = (buf + 1) & (NSTG - 1);
    }

    // ---- epilogue ----
    if (MODE == 0) {
        const int seg = n0 >> 11;           // 0=q, 1=k, 2=v
        const int hh  = (n0 & 2047) >> 7;
#pragma unroll
        for (int am = 0; am < 4; am++) {
#pragma unroll
            for (int cp = 0; cp < 2; cp++) {
                int row = wm * 64 + am * 16 + (lane >> 2) + cp * 8;
                int m = m0 + row;
                int b_ = m >> 11;
                int t  = m & 2047;
                size_t base = (((size_t)(b_ * NH + hh) * T_DIM) + t) * HD;
                if (seg == 0) {
                    __half* dstrow = g_qh + base;
#pragma unroll
                    for (int an = 0; an < 4; an++) {
                        int cl = wn * 32 + an * 8 + (lane & 3) * 2;
                        uint32_t v = pkh(
                            (acc[am][an][cp * 2 + 0] + bias[n0 + cl]) * QK_SCALE,
                            (acc[am][an][cp * 2 + 1] + bias[n0 + cl + 1]) * QK_SCALE);
                        *reinterpret_cast<uint32_t*>(&dstrow[cl]) = v;
                    }
                } else {
                    float* dstrow = ((seg == 1) ? out0 : out1) + base;
                    __half* hrow  = ((seg == 1) ? g_kh : g_vh) + base;
#pragma unroll
                    for (int an = 0; an < 4; an++) {
                        int cl = wn * 32 + an * 8 + (lane & 3) * 2;
                        float2 v;
                        v.x = acc[am][an][cp * 2 + 0] + bias[n0 + cl];
                        v.y = acc[am][an][cp * 2 + 1] + bias[n0 + cl + 1];
                        *reinterpret_cast<float2*>(&dstrow[cl]) = v;
                        *reinterpret_cast<uint32_t*>(&hrow[cl]) = pkh(v.x, v.y);
                    }
                }
            }
        }
    } else {
#pragma unroll
        for (int am = 0; am < 4; am++) {
#pragma unroll
            for (int cp = 0; cp < 2; cp++) {
                int row = wm * 64 + am * 16 + (lane >> 2) + cp * 8;
                int m = m0 + row;
                float* dstrow = out0 + (size_t)m * C_DIM + n0;
#pragma unroll
                for (int an = 0; an < 4; an++) {
                    int cl = wn * 32 + an * 8 + (lane & 3) * 2;
                    float2 v;
                    v.x = acc[am][an][cp * 2 + 0] + bias[n0 + cl];
                    v.y = acc[am][an][cp * 2 + 1] + bias[n0 + cl + 1];
                    *reinterpret_cast<float2*>(&dstrow[cl]) = v;
                }
            }
        }
    }
}

// ---------------------------------------------------------------------------
// FP16 MMA flash attention: register-P, async double-buffered K/V (.cg),
// heavy-first scheduling, 2 CTAs/SM. Q loaded via cp.async (same group as
// first K/V). q pre-scaled, so S needs no per-element scale.
// ---------------------------------------------------------------------------
#define ALH 136

__global__ __launch_bounds__(256, 2) void attn_mma_kernel(int dummy)
{
    extern __shared__ __half sh[];
    __half* Qs = sh;                       // 128 x 136
    __half* Ks = Qs + 128 * ALH;           // 2 x 64 x 136
    __half* Vs = Ks + 2 * 64 * ALH;        // 2 x 64 x 136

    const int tid  = threadIdx.x;
    const int lane = tid & 31;
    const int w    = tid >> 5;
    const int g    = lane >> 3;
    const int l8   = lane & 7;
    const int iq   = (int)gridDim.x - 1 - (int)blockIdx.x;  // heavy first
    const int bh   = blockIdx.y;
    const int b    = bh >> 4;
    const int h    = bh & 15;

    const __half* qp = g_qh + ((size_t)bh * T_DIM + iq * 128) * HD;
    const __half* kp = g_kh + (size_t)bh * T_DIM * HD;
    const __half* vp = g_vh + (size_t)bh * T_DIM * HD;

    const int jmax = 2 * iq + 1;

    auto issue_kv = [&](int bufi, int j) {
        const __half* kb = kp + (size_t)j * 64 * HD;
        const __half* vb = vp + (size_t)j * 64 * HD;
        __half* Kd = Ks + bufi * 64 * ALH;
        __half* Vd = Vs + bufi * 64 * ALH;
#pragma unroll
        for (int r = 0; r < 4; r++) {
            int idx = tid + r * 256;
            int row = idx >> 4;
            int c   = (idx & 15) << 3;
            cpasync16(smem_u32(&Kd[row * ALH + c]), &kb[row * HD + c]);
            cpasync16(smem_u32(&Vd[row * ALH + c]), &vb[row * HD + c]);
        }
        asm volatile("cp.async.commit_group;");
    };

    // Q tile + first K/V tile in one async group
    {
#pragma unroll
        for (int r = 0; r < 8; r++) {
            int idx = tid + r * 256;
            int row = idx >> 4;
            int c   = (idx & 15) << 3;
            cpasync16(smem_u32(&Qs[row * ALH + c]), &qp[row * HD + c]);
        }
        issue_kv(0, 0);   // commits Q+K+V together
    }

    const int r0 = lane >> 2;
    float m_i[2] = {-1e30f, -1e30f};
    float l_i[2] = {0.0f, 0.0f};
    float oacc[16][4];
#pragma unroll
    for (int na = 0; na < 16; na++)
#pragma unroll
        for (int c = 0; c < 4; c++) oacc[na][c] = 0.0f;

    const int qrow_frag = w * 16 + (g & 1) * 8 + l8;

    for (int j = 0; j <= jmax; j++) {
        asm volatile("cp.async.wait_group 0;");
        __syncthreads();
        if (j < jmax) issue_kv((j + 1) & 1, j + 1);

        const __half* Kb = Ks + (j & 1) * 64 * ALH;
        const __half* Vb = Vs + (j & 1) * 64 * ALH;

        float sacc[8][4];
#pragma unroll
        for (int na = 0; na < 8; na++)
#pragma unroll
            for (int c = 0; c < 4; c++) sacc[na][c] = 0.0f;

#pragma unroll
        for (int ks = 0; ks < 8; ks++) {
            uint32_t qf[4];
            {
                int col = ks * 16 + (g >> 1) * 8;
                ldsm4(qf[0], qf[1], qf[2], qf[3],
                      smem_u32(&Qs[qrow_frag * ALH + col]));
            }
#pragma unroll
            for (int np = 0; np < 4; np++) {
                uint32_t bf[4];
                int row = np * 16 + (g >> 1) * 8 + l8;
                int col = ks * 16 + (g & 1) * 8;
                ldsm4(bf[0], bf[1], bf[2], bf[3],
                      smem_u32(&Kb[row * ALH + col]));
                mma_f16(sacc[2 * np],     qf, &bf[0]);
                mma_f16(sacc[2 * np + 1], qf, &bf[2]);
            }
        }

        // causal mask (q pre-scaled; no scale pass needed)
        if (j >= 2 * iq) {
            int qrow0 = iq * 128 + w * 16 + r0;
#pragma unroll
            for (int na = 0; na < 8; na++) {
                int col = j * 64 + na * 8 + 2 * (lane & 3);
                if (col > qrow0)         sacc[na][0] = -1e30f;
                if (col + 1 > qrow0)     sacc[na][1] = -1e30f;
                if (col > qrow0 + 8)     sacc[na][2] = -1e30f;
                if (col + 1 > qrow0 + 8) sacc[na][3] = -1e30f;
            }
        }

        float mt[2] = {-1e30f, -1e30f};
#pragma unroll
        for (int na = 0; na < 8; na++) {
            mt[0] = fmaxf(mt[0], fmaxf(sacc[na][0], sacc[na][1]));
            mt[1] = fmaxf(mt[1], fmaxf(sacc[na][2], sacc[na][3]));
        }
#pragma unroll
        for (int off = 1; off <= 2; off <<= 1) {
            mt[0] = fmaxf(mt[0], __shfl_xor_sync(0xffffffffu, mt[0], off));
            mt[1] = fmaxf(mt[1], __shfl_xor_sync(0xffffffffu, mt[1], off));
        }
        float mnew0 = fmaxf(m_i[0], mt[0]);
        float mnew1 = fmaxf(m_i[1], mt[1]);
        float alpha0 = __expf(m_i[0] - mnew0);
        float alpha1 = __expf(m_i[1] - mnew1);
        m_i[0] = mnew0; m_i[1] = mnew1;

        float sum0 = 0.0f, sum1 = 0.0f;
#pragma unroll
        for (int na = 0; na < 8; na++) {
            sacc[na][0] = __expf(sacc[na][0] - mnew0);
            sacc[na][1] = __expf(sacc[na][1] - mnew0);
            sacc[na][2] = __expf(sacc[na][2] - mnew1);
            sacc[na][3] = __expf(sacc[na][3] - mnew1);
            sum0 += sacc[na][0] + sacc[na][1];
            sum1 += sacc[na][2] + sacc[na][3];
        }
#pragma unroll
        for (int off = 1; off <= 2; off <<= 1) {
            sum0 += __shfl_xor_sync(0xffffffffu, sum0, off);
            sum1 += __shfl_xor_sync(0xffffffffu, sum1, off);
        }
        l_i[0] = l_i[0] * alpha0 + sum0;
        l_i[1] = l_i[1] * alpha1 + sum1;
#pragma unroll
        for (int na = 0; na < 16; na++) {
            oacc[na][0] *= alpha0; oacc[na][1] *= alpha0;
            oacc[na][2] *= alpha1; oacc[na][3] *= alpha1;
        }

#pragma unroll
        for (int kc = 0; kc < 4; kc++) {
            uint32_t pa[4];
            pa[0] = pkh(sacc[2 * kc][0],     sacc[2 * kc][1]);
            pa[1] = pkh(sacc[2 * kc][2],     sacc[2 * kc][3]);
            pa[2] = pkh(sacc[2 * kc + 1][0], sacc[2 * kc + 1][1]);
            pa[3] = pkh(sacc[2 * kc + 1][2], sacc[2 * kc + 1][3]);
#pragma unroll
            for (int ng = 0; ng < 8; ng++) {
                uint32_t vf[4];
                int row = kc * 16 + (g & 1) * 8 + l8;
                int col = ng * 16 + (g >> 1) * 8;
                ldsm4t(vf[0], vf[1], vf[2], vf[3],
                       smem_u32(&Vb[row * ALH + col]));
                mma_f16(oacc[2 * ng],     pa, &vf[0]);
                mma_f16(oacc[2 * ng + 1], pa, &vf[2]);
            }
        }
    }

    float inv0 = 1.0f / l_i[0];
    float inv1 = 1.0f / l_i[1];
    int t0 = iq * 128 + w * 16 + r0;
    int t1 = t0 + 8;
    __half* dst0 = g_yh + ((size_t)(b * T_DIM + t0) * C_DIM) + h * HD;
    __half* dst1 = g_yh + ((size_t)(b * T_DIM + t1) * C_DIM) + h * HD;
#pragma unroll
    for (int na = 0; na < 16; na++) {
        int col = na * 8 + 2 * (lane & 3);
        *reinterpret_cast<uint32_t*>(&dst0[col]) =
            pkh(oacc[na][0] * inv0, oacc[na][1] * inv0);
        *reinterpret_cast<uint32_t*>(&dst1[col]) =
            pkh(oacc[na][2] * inv1, oacc[na][3] * inv1);
    }
}

// ---------------------------------------------------------------------------
extern "C" void kernel_launch(void* const* d_in, const int* in_sizes, int n_in,
                              void* d_out, int out_size)
{
    const float* x    = (const float*)d_in[0];
    const float* Wqkv = (const float*)d_in[1];
    const float* bqkv = (const float*)d_in[2];
    const float* Wout = (const float*)d_in[3];
    const float* bout = (const float*)d_in[4];

    float* y    = (float*)d_out;
    float* kout = y + YELEMS;
    float* vout = y + 2 * YELEMS;

    __half *xh, *wqkvh, *wouth, *yh;
    cudaGetSymbolAddress((void**)&xh,    g_xh);
    cudaGetSymbolAddress((void**)&wqkvh, g_wqkvh);
    cudaGetSymbolAddress((void**)&wouth, g_wouth);
    cudaGetSymbolAddress((void**)&yh,    g_yh);

    const int attn_smem = (128 + 128 + 128) * ALH * 2;   // 104448
    cudaFuncSetAttribute(attn_mma_kernel,
                         cudaFuncAttributeMaxDynamicSharedMemorySize, attn_smem);
    cudaFuncSetAttribute(mma_gemm<0>,
                         cudaFuncAttributeMaxDynamicSharedMemorySize, GEMM_SMEM);
    cudaFuncSetAttribute(mma_gemm<1>,
                         cudaFuncAttributeMaxDynamicSharedMemorySize, GEMM_SMEM);

    // 0) fp16 pre-conversion (single launch, statically partitioned)
    cvt_all_kernel<<<CVT_GRID, 256>>>((const float4*)x, (uint2*)xh,
                                      (const float4*)Wqkv, (uint2*)wqkvh,
                                      (const float4*)Wout, (uint2*)wouth);

    // 1) QKV projection (fp16 MMA, 4-stage .cg ring, swizzled 1D grid)
    mma_gemm<0><<<(3 * C_DIM / BN) * (MTOT / BM), 256, GEMM_SMEM>>>(
        xh, wqkvh, bqkv, kout, vout);

    // 2) causal flash attention (register P, async K/V+Q, 2 CTA/SM) -> g_yh
    attn_mma_kernel<<<dim3(T_DIM / 128, B_DIM * NH), 256, attn_smem>>>(0);

    // 3) output projection -> y (swizzled 1D grid)
    mma_gemm<1><<<(C_DIM / BN) * (MTOT / BM), 256, GEMM_SMEM>>>(
        yh, wouth, bout, y, nullptr);
}